// round 7
// baseline (speedup 1.0000x reference)
#include <cuda_runtime.h>
#include <cstdint>
#include <cstddef>

#define VOCAB   1024
#define HIDDEN  1024
#define BATCH   4096
#define KDIM    2048
#define NDIM    4096

#define MT      128
#define NT      256     // gathered gate columns (64 hidden units x 4 gates)
#define KT      32
#define STAGES  3
#define NKITER  64      // KDIM / KT
#define THREADS 512

#define OFF_BIAS  0                       // 256 floats
#define OFF_STAGE 1024
#define A_BYTES   (MT * 128)              // 16384
#define B_BYTES   (NT * 128)              // 32768
#define STAGE_BYTES (A_BYTES + B_BYTES)   // 49152
#define SMEM_TOTAL  (OFF_STAGE + STAGES * STAGE_BYTES)  // 148480

// Transposed + tf32(RN)-rounded weights: g_WT[n][k] = rn_tf32([W;V][k][n])
__device__ float g_WT[(size_t)NDIM * KDIM];

// ---------------- helpers ----------------
__device__ __forceinline__ uint32_t smem_u32(const void* p) {
    uint32_t a;
    asm("{ .reg .u64 t; cvta.to.shared.u64 t, %1; cvt.u32.u64 %0, t; }" : "=r"(a) : "l"(p));
    return a;
}
__device__ __forceinline__ uint32_t sw128(uint32_t o) { return o ^ ((o >> 3) & 0x70); }
__device__ __forceinline__ uint32_t cvt_tf32(float f) {
    uint32_t r;
    asm("cvt.rna.tf32.f32 %0, %1;" : "=r"(r) : "f"(f));
    return r;
}
__device__ __forceinline__ void ldsm4(uint32_t* r, uint32_t addr) {
    asm volatile("ldmatrix.sync.aligned.m8n8.x4.shared.b16 {%0,%1,%2,%3}, [%4];"
                 : "=r"(r[0]), "=r"(r[1]), "=r"(r[2]), "=r"(r[3]) : "r"(addr));
}
__device__ __forceinline__ void mma8(float* d, const uint32_t* a, uint32_t b0, uint32_t b1) {
    asm volatile("mma.sync.aligned.m16n8k8.row.col.f32.tf32.tf32.f32 "
                 "{%0,%1,%2,%3}, {%4,%5,%6,%7}, {%8,%9}, {%0,%1,%2,%3};"
                 : "+f"(d[0]), "+f"(d[1]), "+f"(d[2]), "+f"(d[3])
                 : "r"(a[0]), "r"(a[1]), "r"(a[2]), "r"(a[3]), "r"(b0), "r"(b1));
}
__device__ __forceinline__ float sigmoidf_fast(float x) {
    return 1.f / (1.f + __expf(-x));
}
__device__ __forceinline__ float tanhf_fast(float x) {
    return 2.f / (1.f + __expf(-2.f * x)) - 1.f;
}

// ---------------- prep: transpose + tf32-round weights ----------------
__global__ void prep_transpose(const float* __restrict__ W, const float* __restrict__ V) {
    __shared__ float tile[32][33];
    int n0 = blockIdx.x * 32;
    int k0 = blockIdx.y * 32;
    int tx = threadIdx.x, ty = threadIdx.y;   // 32 x 8
#pragma unroll
    for (int i = 0; i < 4; i++) {
        int k = k0 + ty + i * 8;
        const float* src = (k < VOCAB) ? (W + (size_t)k * NDIM)
                                       : (V + (size_t)(k - VOCAB) * NDIM);
        tile[ty + i * 8][tx] = src[n0 + tx];
    }
    __syncthreads();
#pragma unroll
    for (int i = 0; i < 4; i++) {
        int n = n0 + ty + i * 8;
        ((uint32_t*)g_WT)[(size_t)n * KDIM + k0 + tx] = cvt_tf32(tile[tx][ty + i * 8]);
    }
}

// ---------------- stage loader ----------------
// B tile row r encodes: gate = bit0 | bit3<<1 ; jj = bits1-2 | bits4-5<<2 | bits6-7<<4
__device__ __forceinline__ void load_stage(uint8_t* smem, uint32_t sbase, int kt,
                                           const float* __restrict__ x,
                                           const float* __restrict__ hh,
                                           int m0, int j0, int tid) {
    int s = kt % STAGES;
    uint32_t a_off = sbase + OFF_STAGE + s * STAGE_BYTES;
    uint32_t b_off = a_off + A_BYTES;

    // A: [x|h] tile, 128 rows x 32 k (K-major, SW128), RN-round to tf32 on the fly
    const float* Abase = (kt < 32) ? x : hh;
    int kk0 = (kt * KT) & (VOCAB - 1);
#pragma unroll
    for (int r = 0; r < 2; r++) {
        int idx = tid + THREADS * r;       // 0..1023
        int row = idx >> 3, cc = idx & 7;
        const float4 v = *(const float4*)(Abase + (size_t)(m0 + row) * VOCAB + kk0 + cc * 4);
        uint32_t t0 = cvt_tf32(v.x), t1 = cvt_tf32(v.y), t2 = cvt_tf32(v.z), t3 = cvt_tf32(v.w);
        uint32_t dst = a_off + sw128(row * 128 + cc * 16);
        asm volatile("st.shared.v4.b32 [%0], {%1,%2,%3,%4};"
                     :: "r"(dst), "r"(t0), "r"(t1), "r"(t2), "r"(t3) : "memory");
    }
    // B: gate-interleaved K-major rows from pre-transposed WT, async 16B copies
#pragma unroll
    for (int r = 0; r < 4; r++) {
        int idx = tid + THREADS * r;       // 0..2047
        int row = idx >> 3, cc = idx & 7;  // row 0..255
        int gate = (row & 1) | (((row >> 3) & 1) << 1);
        int jj   = ((row >> 1) & 3) | (((row >> 4) & 3) << 2) | ((row >> 6) << 4);
        int n = gate * HIDDEN + j0 + jj;
        const float* src = g_WT + (size_t)n * KDIM + kt * KT + cc * 4;
        uint32_t dst = b_off + sw128(row * 128 + cc * 16);
        asm volatile("cp.async.cg.shared.global [%0], [%1], 16;"
                     :: "r"(dst), "l"(src) : "memory");
    }
}

// ---------------- fused LSTM GEMM + gates ----------------
__global__ void __launch_bounds__(THREADS, 1)
lstm_gemm(const float* __restrict__ x, const float* __restrict__ h,
          const float* __restrict__ c, const float* __restrict__ b,
          float* __restrict__ out) {
    extern __shared__ uint8_t smem[];
    uint32_t sbase = smem_u32(smem);
    int tid = threadIdx.x;
    int wid = tid >> 5, lane = tid & 31;
    int warp_m = wid & 3;      // 4 warps in M (32 rows each)
    int warp_n = wid >> 2;     // 4 warps in N (64 gathered cols each)

    int m0 = blockIdx.x * MT;   // 32 M tiles
    int j0 = blockIdx.y * 64;   // 16 hidden tiles

    // bias into smem: bias_s[gate*64 + jj]
    if (tid < 256) {
        int gate = tid >> 6, jj = tid & 63;
        ((float*)(smem + OFF_BIAS))[tid] = b[gate * HIDDEN + j0 + jj];
    }

    // ldmatrix per-thread address components (pre-swizzle row bases + xor masks)
    uint32_t aoff[2], axor[2];
    uint32_t ahi16 = ((lane >> 4) & 1) * 16;
#pragma unroll
    for (int mb = 0; mb < 2; mb++) {
        int arow = warp_m * 32 + mb * 16 + ((lane >> 3) & 1) * 8 + (lane & 7);
        aoff[mb] = arow * 128;
        axor[mb] = (arow & 7) << 4;
    }
    uint32_t boff[4], bxor[4];
    uint32_t bhi16 = ((lane >> 3) & 1) * 16;
#pragma unroll
    for (int p = 0; p < 4; p++) {
        int brow = warp_n * 64 + p * 16 + ((lane >> 4) & 1) * 8 + (lane & 7);
        boff[p] = brow * 128;
        bxor[p] = (brow & 7) << 4;
    }

    float d[2][8][4];
#pragma unroll
    for (int mb = 0; mb < 2; mb++)
#pragma unroll
        for (int nb = 0; nb < 8; nb++)
#pragma unroll
            for (int e = 0; e < 4; e++) d[mb][nb][e] = 0.f;

    // prologue: stages 0..STAGES-2
#pragma unroll
    for (int s = 0; s < STAGES - 1; s++) {
        load_stage(smem, sbase, s, x, h, m0, j0, tid);
        asm volatile("cp.async.commit_group;" ::: "memory");
    }

    for (int kt = 0; kt < NKITER; kt++) {
        asm volatile("cp.async.wait_group %0;" :: "n"(STAGES - 2) : "memory");
        __syncthreads();

        int lkt = kt + STAGES - 1;
        if (lkt < NKITER) load_stage(smem, sbase, lkt, x, h, m0, j0, tid);
        asm volatile("cp.async.commit_group;" ::: "memory");

        uint32_t stage_a = sbase + OFF_STAGE + (kt % STAGES) * STAGE_BYTES;
        uint32_t stage_b = stage_a + A_BYTES;

#pragma unroll
        for (int s = 0; s < 4; s++) {
            uint32_t kb = (uint32_t)(s * 32);
            uint32_t afr[2][4], bfr[4][4];
#pragma unroll
            for (int mb = 0; mb < 2; mb++)
                ldsm4(afr[mb], stage_a + aoff[mb] + ((kb + ahi16) ^ axor[mb]));
#pragma unroll
            for (int p = 0; p < 4; p++)
                ldsm4(bfr[p], stage_b + boff[p] + ((kb + bhi16) ^ bxor[p]));
#pragma unroll
            for (int mb = 0; mb < 2; mb++)
#pragma unroll
                for (int p = 0; p < 4; p++) {
                    mma8(d[mb][2 * p],     afr[mb], bfr[p][0], bfr[p][1]);
                    mma8(d[mb][2 * p + 1], afr[mb], bfr[p][2], bfr[p][3]);
                }
        }
    }

    // ---- fused epilogue straight from register accumulators ----
    const float* bias_s = (const float*)(smem + OFF_BIAS);
    int q = lane & 3, rg = lane >> 2;
    float* hout_g = out;
    float* cout_g = out + (size_t)BATCH * HIDDEN;
#pragma unroll
    for (int mb = 0; mb < 2; mb++) {
#pragma unroll
        for (int u = 0; u < 4; u++) {
            int jj = warp_n * 16 + q + u * 4;          // 0..63
            float bi = bias_s[jj];
            float bf = bias_s[64 + jj];
            float bo = bias_s[128 + jj];
            float bg = bias_s[192 + jj];
#pragma unroll
            for (int h2 = 0; h2 < 2; h2++) {
                int r = m0 + warp_m * 32 + mb * 16 + h2 * 8 + rg;
                float ai = d[mb][2 * u][2 * h2]         + bi;
                float af = d[mb][2 * u][2 * h2 + 1]     + bf;
                float ao = d[mb][2 * u + 1][2 * h2]     + bo;
                float ag = d[mb][2 * u + 1][2 * h2 + 1] + bg;
                float ig = sigmoidf_fast(ai);
                float fg = sigmoidf_fast(af);
                float og = sigmoidf_fast(ao);
                float gg = tanhf_fast(ag);
                size_t gidx = (size_t)r * HIDDEN + j0 + jj;
                float cin  = __ldg(c + gidx);
                float cout = ig * gg + fg * cin;
                hout_g[gidx] = og * tanhf_fast(cout);
                cout_g[gidx] = cout;
            }
        }
    }
}

extern "C" void kernel_launch(void* const* d_in, const int* in_sizes, int n_in,
                              void* d_out, int out_size) {
    const float* x = (const float*)d_in[0];
    const float* h = (const float*)d_in[1];
    const float* c = (const float*)d_in[2];
    const float* W = (const float*)d_in[3];
    const float* V = (const float*)d_in[4];
    const float* b = (const float*)d_in[5];
    float* out = (float*)d_out;

    cudaFuncSetAttribute(lstm_gemm, cudaFuncAttributeMaxDynamicSharedMemorySize, SMEM_TOTAL);

    prep_transpose<<<dim3(NDIM / 32, KDIM / 32), dim3(32, 8)>>>(W, V);
    lstm_gemm<<<dim3(BATCH / MT, HIDDEN / 64), THREADS, SMEM_TOTAL>>>(x, h, c, b, out);
}

// round 8
// speedup vs baseline: 2.0205x; 2.0205x over previous
#include <cuda_runtime.h>
#include <cstdint>
#include <cstddef>

#define VOCAB   1024
#define HIDDEN  1024
#define BATCH   4096
#define KDIM    2048
#define NDIM    4096

#define MT      128
#define NT      128     // gathered gate columns (32 hidden units x 4 gates)
#define KT      32
#define STAGES  3
#define NKITER  64      // KDIM / KT
#define THREADS 256

#define OFF_BIAS  0                       // 128 floats
#define OFF_STAGE 1024
#define A_BYTES   (MT * 128)              // 16384
#define B_BYTES   (NT * 128)              // 16384
#define STAGE_BYTES (A_BYTES + B_BYTES)   // 32768
#define SMEM_TOTAL  (OFF_STAGE + STAGES * STAGE_BYTES)  // 99328  (x2 CTAs = 198656 <= 228KB)

// Prepped operands (tf32 RN-rounded), both L2-resident (64 MB total vs 126 MB L2):
//   g_WT[n][k] = rn_tf32([W;V][k][n])   (transposed to K-major)
//   g_A[m][k]  = rn_tf32([x|h][m][k])   (already K-major, just rounded+fused)
__device__ float g_WT[(size_t)NDIM * KDIM];
__device__ float g_A [(size_t)BATCH * KDIM];

// ---------------- helpers ----------------
__device__ __forceinline__ uint32_t smem_u32(const void* p) {
    uint32_t a;
    asm("{ .reg .u64 t; cvta.to.shared.u64 t, %1; cvt.u32.u64 %0, t; }" : "=r"(a) : "l"(p));
    return a;
}
__device__ __forceinline__ uint32_t sw128(uint32_t o) { return o ^ ((o >> 3) & 0x70); }
__device__ __forceinline__ uint32_t cvt_tf32(float f) {
    uint32_t r;
    asm("cvt.rna.tf32.f32 %0, %1;" : "=r"(r) : "f"(f));
    return r;
}
__device__ __forceinline__ void ldsm4(uint32_t* r, uint32_t addr) {
    asm volatile("ldmatrix.sync.aligned.m8n8.x4.shared.b16 {%0,%1,%2,%3}, [%4];"
                 : "=r"(r[0]), "=r"(r[1]), "=r"(r[2]), "=r"(r[3]) : "r"(addr));
}
__device__ __forceinline__ void mma8(float* d, const uint32_t* a, uint32_t b0, uint32_t b1) {
    asm volatile("mma.sync.aligned.m16n8k8.row.col.f32.tf32.tf32.f32 "
                 "{%0,%1,%2,%3}, {%4,%5,%6,%7}, {%8,%9}, {%0,%1,%2,%3};"
                 : "+f"(d[0]), "+f"(d[1]), "+f"(d[2]), "+f"(d[3])
                 : "r"(a[0]), "r"(a[1]), "r"(a[2]), "r"(a[3]), "r"(b0), "r"(b1));
}
__device__ __forceinline__ float sigmoidf_fast(float x) {
    return 1.f / (1.f + __expf(-x));
}
__device__ __forceinline__ float tanhf_fast(float x) {
    return 2.f / (1.f + __expf(-2.f * x)) - 1.f;
}

// ---------------- prep: transpose + tf32-round weights ----------------
__global__ void prep_transpose(const float* __restrict__ W, const float* __restrict__ V) {
    __shared__ float tile[32][33];
    int n0 = blockIdx.x * 32;
    int k0 = blockIdx.y * 32;
    int tx = threadIdx.x, ty = threadIdx.y;   // 32 x 8
#pragma unroll
    for (int i = 0; i < 4; i++) {
        int k = k0 + ty + i * 8;
        const float* src = (k < VOCAB) ? (W + (size_t)k * NDIM)
                                       : (V + (size_t)(k - VOCAB) * NDIM);
        tile[ty + i * 8][tx] = src[n0 + tx];
    }
    __syncthreads();
#pragma unroll
    for (int i = 0; i < 4; i++) {
        int n = n0 + ty + i * 8;
        ((uint32_t*)g_WT)[(size_t)n * KDIM + k0 + tx] = cvt_tf32(tile[tx][ty + i * 8]);
    }
}

// ---------------- prep: fuse [x|h] + tf32-round (no transpose needed) ----------------
__global__ void prep_A(const float* __restrict__ x, const float* __restrict__ h) {
    size_t i = ((size_t)blockIdx.x * 256 + threadIdx.x) * 4;   // over BATCH*KDIM
    int row = (int)(i / KDIM);
    int col = (int)(i % KDIM);
    const float* src = (col < VOCAB) ? (x + (size_t)row * VOCAB + col)
                                     : (h + (size_t)row * VOCAB + (col - VOCAB));
    float4 v = *(const float4*)src;
    uint4 t;
    t.x = cvt_tf32(v.x); t.y = cvt_tf32(v.y); t.z = cvt_tf32(v.z); t.w = cvt_tf32(v.w);
    *(uint4*)((uint32_t*)g_A + i) = t;
}

// ---------------- stage loader: pure cp.async, zero register data path ----------------
// B tile row r encodes: gate = bit0 | bit3<<1 ; jj = bits1-2 | bits4-5<<2 | bit6<<4
__device__ __forceinline__ void load_stage(uint32_t sbase, int kt, int m0, int j0, int tid) {
    int s = kt % STAGES;
    uint32_t a_off = sbase + OFF_STAGE + s * STAGE_BYTES;
    uint32_t b_off = a_off + A_BYTES;
    int kk = kt * KT;
#pragma unroll
    for (int r = 0; r < 4; r++) {
        int idx = tid + THREADS * r;       // 0..1023
        int row = idx >> 3, cc = idx & 7;  // row 0..127, 16B chunk 0..7
        uint32_t sw = sw128(row * 128 + cc * 16);

        const float* srcA = g_A + (size_t)(m0 + row) * KDIM + kk + cc * 4;
        asm volatile("cp.async.cg.shared.global [%0], [%1], 16;"
                     :: "r"(a_off + sw), "l"(srcA) : "memory");

        int gate = (row & 1) | (((row >> 3) & 1) << 1);
        int jj   = ((row >> 1) & 3) | (((row >> 4) & 3) << 2) | ((row >> 6) << 4);
        const float* srcB = g_WT + (size_t)(gate * HIDDEN + j0 + jj) * KDIM + kk + cc * 4;
        asm volatile("cp.async.cg.shared.global [%0], [%1], 16;"
                     :: "r"(b_off + sw), "l"(srcB) : "memory");
    }
}

// ---------------- fused LSTM GEMM + gates ----------------
__global__ void __launch_bounds__(THREADS, 2)
lstm_gemm(const float* __restrict__ c, const float* __restrict__ b,
          float* __restrict__ out) {
    extern __shared__ uint8_t smem[];
    uint32_t sbase = smem_u32(smem);
    int tid = threadIdx.x;
    int wid = tid >> 5, lane = tid & 31;
    int warp_m = wid & 3;      // 4 warps in M (32 rows each)
    int warp_n = wid >> 2;     // 2 warps in N (64 gathered cols each)

    int m0 = blockIdx.x * MT;   // 32 M tiles
    int j0 = blockIdx.y * 32;   // 32 hidden tiles (32 hidden units each)

    // bias into smem: bias_s[gate*32 + jj]
    if (tid < 128) {
        int gate = tid >> 5, jj = tid & 31;
        ((float*)(smem + OFF_BIAS))[tid] = b[gate * HIDDEN + j0 + jj];
    }

    // ldmatrix per-thread address components (pre-swizzle row bases + xor masks)
    uint32_t aoff[2], axor[2];
    uint32_t ahi16 = ((lane >> 4) & 1) * 16;
#pragma unroll
    for (int mb = 0; mb < 2; mb++) {
        int arow = warp_m * 32 + mb * 16 + ((lane >> 3) & 1) * 8 + (lane & 7);
        aoff[mb] = arow * 128;
        axor[mb] = (arow & 7) << 4;
    }
    uint32_t boff[4], bxor[4];
    uint32_t bhi16 = ((lane >> 3) & 1) * 16;
#pragma unroll
    for (int p = 0; p < 4; p++) {
        int brow = warp_n * 64 + p * 16 + ((lane >> 4) & 1) * 8 + (lane & 7);
        boff[p] = brow * 128;
        bxor[p] = (brow & 7) << 4;
    }

    float d[2][8][4];
#pragma unroll
    for (int mb = 0; mb < 2; mb++)
#pragma unroll
        for (int nb = 0; nb < 8; nb++)
#pragma unroll
            for (int e = 0; e < 4; e++) d[mb][nb][e] = 0.f;

    // prologue: stages 0..STAGES-2
#pragma unroll
    for (int s = 0; s < STAGES - 1; s++) {
        load_stage(sbase, s, m0, j0, tid);
        asm volatile("cp.async.commit_group;" ::: "memory");
    }

    for (int kt = 0; kt < NKITER; kt++) {
        asm volatile("cp.async.wait_group %0;" :: "n"(STAGES - 2) : "memory");
        __syncthreads();

        int lkt = kt + STAGES - 1;
        if (lkt < NKITER) load_stage(sbase, lkt, m0, j0, tid);
        asm volatile("cp.async.commit_group;" ::: "memory");

        uint32_t stage_a = sbase + OFF_STAGE + (kt % STAGES) * STAGE_BYTES;
        uint32_t stage_b = stage_a + A_BYTES;

#pragma unroll
        for (int s = 0; s < 4; s++) {
            uint32_t kb = (uint32_t)(s * 32);
            uint32_t afr[2][4], bfr[4][4];
#pragma unroll
            for (int mb = 0; mb < 2; mb++)
                ldsm4(afr[mb], stage_a + aoff[mb] + ((kb + ahi16) ^ axor[mb]));
#pragma unroll
            for (int p = 0; p < 4; p++)
                ldsm4(bfr[p], stage_b + boff[p] + ((kb + bhi16) ^ bxor[p]));
#pragma unroll
            for (int mb = 0; mb < 2; mb++)
#pragma unroll
                for (int p = 0; p < 4; p++) {
                    mma8(d[mb][2 * p],     afr[mb], bfr[p][0], bfr[p][1]);
                    mma8(d[mb][2 * p + 1], afr[mb], bfr[p][2], bfr[p][3]);
                }
        }
    }

    // ---- fused epilogue straight from register accumulators ----
    const float* bias_s = (const float*)(smem + OFF_BIAS);
    int q = lane & 3, rg = lane >> 2;
    float* hout_g = out;
    float* cout_g = out + (size_t)BATCH * HIDDEN;
#pragma unroll
    for (int mb = 0; mb < 2; mb++) {
#pragma unroll
        for (int u = 0; u < 4; u++) {
            int jj = warp_n * 16 + q + u * 4;          // 0..31
            float bi = bias_s[jj];
            float bf = bias_s[32 + jj];
            float bo = bias_s[64 + jj];
            float bg = bias_s[96 + jj];
#pragma unroll
            for (int h2 = 0; h2 < 2; h2++) {
                int r = m0 + warp_m * 32 + mb * 16 + h2 * 8 + rg;
                float ai = d[mb][2 * u][2 * h2]         + bi;
                float af = d[mb][2 * u][2 * h2 + 1]     + bf;
                float ao = d[mb][2 * u + 1][2 * h2]     + bo;
                float ag = d[mb][2 * u + 1][2 * h2 + 1] + bg;
                float ig = sigmoidf_fast(ai);
                float fg = sigmoidf_fast(af);
                float og = sigmoidf_fast(ao);
                float gg = tanhf_fast(ag);
                size_t gidx = (size_t)r * HIDDEN + j0 + jj;
                float cin  = __ldg(c + gidx);
                float cout = ig * gg + fg * cin;
                hout_g[gidx] = og * tanhf_fast(cout);
                cout_g[gidx] = cout;
            }
        }
    }
}

extern "C" void kernel_launch(void* const* d_in, const int* in_sizes, int n_in,
                              void* d_out, int out_size) {
    const float* x = (const float*)d_in[0];
    const float* h = (const float*)d_in[1];
    const float* c = (const float*)d_in[2];
    const float* W = (const float*)d_in[3];
    const float* V = (const float*)d_in[4];
    const float* b = (const float*)d_in[5];
    float* out = (float*)d_out;

    cudaFuncSetAttribute(lstm_gemm, cudaFuncAttributeMaxDynamicSharedMemorySize, SMEM_TOTAL);

    prep_transpose<<<dim3(NDIM / 32, KDIM / 32), dim3(32, 8)>>>(W, V);
    prep_A<<<(int)(((size_t)BATCH * KDIM / 4) / 256), 256>>>(x, h);
    lstm_gemm<<<dim3(BATCH / MT, HIDDEN / 32), THREADS, SMEM_TOTAL>>>(c, b, out);
}

// round 9
// speedup vs baseline: 3.5269x; 1.7456x over previous
#include <cuda_runtime.h>
#include <cuda_fp16.h>
#include <cstdint>
#include <cstddef>

#define VOCAB   1024
#define HIDDEN  1024
#define BATCH   4096
#define KDIM    2048
#define NDIM    4096

#define MT      128
#define NT      128     // gathered gate columns (32 hidden units x 4 gates)
#define KT      64      // fp16: 64 k per stage (128B rows)
#define STAGES  3
#define NKITER  32      // KDIM / KT
#define THREADS 256

#define OFF_BIAS  0                       // 128 floats
#define OFF_STAGE 1024
#define A_BYTES   (MT * 128)              // 16384
#define B_BYTES   (NT * 128)              // 16384
#define STAGE_BYTES (A_BYTES + B_BYTES)   // 32768
#define SMEM_TOTAL  (OFF_STAGE + STAGES * STAGE_BYTES)  // 99328  (x2 CTAs fits 228KB)

// Prepped fp16 operands (RN-rounded), 32 MB total -> L2-resident:
//   g_WT[n][k] = rn_f16([W;V][k][n])   (transposed to K-major)
//   g_A[m][k]  = rn_f16([x|h][m][k])   (K-major, fused + rounded)
__device__ __half g_WT[(size_t)NDIM * KDIM];
__device__ __half g_A [(size_t)BATCH * KDIM];

// ---------------- helpers ----------------
__device__ __forceinline__ uint32_t smem_u32(const void* p) {
    uint32_t a;
    asm("{ .reg .u64 t; cvta.to.shared.u64 t, %1; cvt.u32.u64 %0, t; }" : "=r"(a) : "l"(p));
    return a;
}
__device__ __forceinline__ uint32_t sw128(uint32_t o) { return o ^ ((o >> 3) & 0x70); }
__device__ __forceinline__ void ldsm4(uint32_t* r, uint32_t addr) {
    asm volatile("ldmatrix.sync.aligned.m8n8.x4.shared.b16 {%0,%1,%2,%3}, [%4];"
                 : "=r"(r[0]), "=r"(r[1]), "=r"(r[2]), "=r"(r[3]) : "r"(addr));
}
__device__ __forceinline__ void mma16(float* d, const uint32_t* a, uint32_t b0, uint32_t b1) {
    asm volatile("mma.sync.aligned.m16n8k16.row.col.f32.f16.f16.f32 "
                 "{%0,%1,%2,%3}, {%4,%5,%6,%7}, {%8,%9}, {%0,%1,%2,%3};"
                 : "+f"(d[0]), "+f"(d[1]), "+f"(d[2]), "+f"(d[3])
                 : "r"(a[0]), "r"(a[1]), "r"(a[2]), "r"(a[3]), "r"(b0), "r"(b1));
}
__device__ __forceinline__ float sigmoidf_fast(float x) {
    return 1.f / (1.f + __expf(-x));
}
__device__ __forceinline__ float tanhf_fast(float x) {
    return 2.f / (1.f + __expf(-2.f * x)) - 1.f;
}

// ---------------- prep: transpose + fp16-round weights ----------------
__global__ void prep_transpose(const float* __restrict__ W, const float* __restrict__ V) {
    __shared__ float tile[32][33];
    int n0 = blockIdx.x * 32;
    int k0 = blockIdx.y * 32;
    int tx = threadIdx.x, ty = threadIdx.y;   // 32 x 8
#pragma unroll
    for (int i = 0; i < 4; i++) {
        int k = k0 + ty + i * 8;
        const float* src = (k < VOCAB) ? (W + (size_t)k * NDIM)
                                       : (V + (size_t)(k - VOCAB) * NDIM);
        tile[ty + i * 8][tx] = src[n0 + tx];
    }
    __syncthreads();
#pragma unroll
    for (int i = 0; i < 4; i++) {
        int n = n0 + ty + i * 8;
        g_WT[(size_t)n * KDIM + k0 + tx] = __float2half_rn(tile[tx][ty + i * 8]);
    }
}

// ---------------- prep: fuse [x|h] + fp16-round (no transpose needed) ----------------
__global__ void prep_A(const float* __restrict__ x, const float* __restrict__ h) {
    size_t i = ((size_t)blockIdx.x * 256 + threadIdx.x) * 4;   // over BATCH*KDIM halfs
    int row = (int)(i / KDIM);
    int col = (int)(i % KDIM);
    const float* src = (col < VOCAB) ? (x + (size_t)row * VOCAB + col)
                                     : (h + (size_t)row * VOCAB + (col - VOCAB));
    float4 v = *(const float4*)src;
    __half2* dst = (__half2*)(g_A + i);
    dst[0] = __floats2half2_rn(v.x, v.y);
    dst[1] = __floats2half2_rn(v.z, v.w);
}

// ---------------- stage loader: pure cp.async, zero register data path ----------------
// B tile row r encodes: gate = bit0 | bit3<<1 ; jj = bits1-2 | bits4-5<<2 | bit6<<4
__device__ __forceinline__ void load_stage(uint32_t sbase, int kt, int m0, int j0, int tid) {
    int s = kt % STAGES;
    uint32_t a_off = sbase + OFF_STAGE + s * STAGE_BYTES;
    uint32_t b_off = a_off + A_BYTES;
    int kk = kt * KT;                      // in halfs
#pragma unroll
    for (int r = 0; r < 4; r++) {
        int idx = tid + THREADS * r;       // 0..1023
        int row = idx >> 3, cc = idx & 7;  // row 0..127, 16B chunk 0..7
        uint32_t sw = sw128(row * 128 + cc * 16);

        const __half* srcA = g_A + (size_t)(m0 + row) * KDIM + kk + cc * 8;
        asm volatile("cp.async.cg.shared.global [%0], [%1], 16;"
                     :: "r"(a_off + sw), "l"(srcA) : "memory");

        int gate = (row & 1) | (((row >> 3) & 1) << 1);
        int jj   = ((row >> 1) & 3) | (((row >> 4) & 3) << 2) | ((row >> 6) << 4);
        const __half* srcB = g_WT + (size_t)(gate * HIDDEN + j0 + jj) * KDIM + kk + cc * 8;
        asm volatile("cp.async.cg.shared.global [%0], [%1], 16;"
                     :: "r"(b_off + sw), "l"(srcB) : "memory");
    }
}

// ---------------- fused LSTM GEMM + gates ----------------
__global__ void __launch_bounds__(THREADS, 2)
lstm_gemm(const float* __restrict__ c, const float* __restrict__ b,
          float* __restrict__ out) {
    extern __shared__ uint8_t smem[];
    uint32_t sbase = smem_u32(smem);
    int tid = threadIdx.x;
    int wid = tid >> 5, lane = tid & 31;
    int warp_m = wid & 3;      // 4 warps in M (32 rows each)
    int warp_n = wid >> 2;     // 2 warps in N (64 gathered cols each)

    int m0 = blockIdx.x * MT;   // 32 M tiles
    int j0 = blockIdx.y * 32;   // 32 hidden tiles (32 hidden units each)

    // bias into smem: bias_s[gate*32 + jj]
    if (tid < 128) {
        int gate = tid >> 5, jj = tid & 31;
        ((float*)(smem + OFF_BIAS))[tid] = b[gate * HIDDEN + j0 + jj];
    }

    // ldmatrix per-thread address components (pre-swizzle row bases + xor masks)
    // A m16k16 frag: lanes0-7 rows+0..7/k-lo, 8-15 rows+8/k-lo, 16-23 rows/k-hi, 24-31 rows+8/k-hi
    uint32_t aoff[2], axor[2];
    uint32_t ahi16 = ((lane >> 4) & 1) * 16;
#pragma unroll
    for (int mb = 0; mb < 2; mb++) {
        int arow = warp_m * 32 + mb * 16 + ((lane >> 3) & 1) * 8 + (lane & 7);
        aoff[mb] = arow * 128;
        axor[mb] = (arow & 7) << 4;
    }
    // B n8k16 frag pairs: lanes0-7 n+0..7/k-lo, 8-15 n+0..7/k-hi, 16-23 n+8/k-lo, 24-31 n+8/k-hi
    uint32_t boff[4], bxor[4];
    uint32_t bhi16 = ((lane >> 3) & 1) * 16;
#pragma unroll
    for (int p = 0; p < 4; p++) {
        int brow = warp_n * 64 + p * 16 + ((lane >> 4) & 1) * 8 + (lane & 7);
        boff[p] = brow * 128;
        bxor[p] = (brow & 7) << 4;
    }

    float d[2][8][4];
#pragma unroll
    for (int mb = 0; mb < 2; mb++)
#pragma unroll
        for (int nb = 0; nb < 8; nb++)
#pragma unroll
            for (int e = 0; e < 4; e++) d[mb][nb][e] = 0.f;

    // prologue: stages 0..STAGES-2
#pragma unroll
    for (int s = 0; s < STAGES - 1; s++) {
        load_stage(sbase, s, m0, j0, tid);
        asm volatile("cp.async.commit_group;" ::: "memory");
    }

    for (int kt = 0; kt < NKITER; kt++) {
        asm volatile("cp.async.wait_group %0;" :: "n"(STAGES - 2) : "memory");
        __syncthreads();

        int lkt = kt + STAGES - 1;
        if (lkt < NKITER) load_stage(sbase, lkt, m0, j0, tid);
        asm volatile("cp.async.commit_group;" ::: "memory");

        uint32_t stage_a = sbase + OFF_STAGE + (kt % STAGES) * STAGE_BYTES;
        uint32_t stage_b = stage_a + A_BYTES;

#pragma unroll
        for (int s = 0; s < 4; s++) {        // 4 k-steps of 16 halfs (32B each)
            uint32_t kb = (uint32_t)(s * 32);
            uint32_t afr[2][4], bfr[4][4];
#pragma unroll
            for (int mb = 0; mb < 2; mb++)
                ldsm4(afr[mb], stage_a + aoff[mb] + ((kb + ahi16) ^ axor[mb]));
#pragma unroll
            for (int p = 0; p < 4; p++)
                ldsm4(bfr[p], stage_b + boff[p] + ((kb + bhi16) ^ bxor[p]));
#pragma unroll
            for (int mb = 0; mb < 2; mb++)
#pragma unroll
                for (int p = 0; p < 4; p++) {
                    mma16(d[mb][2 * p],     afr[mb], bfr[p][0], bfr[p][1]);
                    mma16(d[mb][2 * p + 1], afr[mb], bfr[p][2], bfr[p][3]);
                }
        }
    }

    // ---- fused epilogue straight from register accumulators ----
    const float* bias_s = (const float*)(smem + OFF_BIAS);
    int q = lane & 3, rg = lane >> 2;
    float* hout_g = out;
    float* cout_g = out + (size_t)BATCH * HIDDEN;
#pragma unroll
    for (int mb = 0; mb < 2; mb++) {
#pragma unroll
        for (int u = 0; u < 4; u++) {
            int jj = warp_n * 16 + q + u * 4;          // 0..31
            float bi = bias_s[jj];
            float bf = bias_s[32 + jj];
            float bo = bias_s[64 + jj];
            float bg = bias_s[96 + jj];
#pragma unroll
            for (int h2 = 0; h2 < 2; h2++) {
                int r = m0 + warp_m * 32 + mb * 16 + h2 * 8 + rg;
                float ai = d[mb][2 * u][2 * h2]         + bi;
                float af = d[mb][2 * u][2 * h2 + 1]     + bf;
                float ao = d[mb][2 * u + 1][2 * h2]     + bo;
                float ag = d[mb][2 * u + 1][2 * h2 + 1] + bg;
                float ig = sigmoidf_fast(ai);
                float fg = sigmoidf_fast(af);
                float og = sigmoidf_fast(ao);
                float gg = tanhf_fast(ag);
                size_t gidx = (size_t)r * HIDDEN + j0 + jj;
                float cin  = __ldg(c + gidx);
                float cout = ig * gg + fg * cin;
                hout_g[gidx] = og * tanhf_fast(cout);
                cout_g[gidx] = cout;
            }
        }
    }
}

extern "C" void kernel_launch(void* const* d_in, const int* in_sizes, int n_in,
                              void* d_out, int out_size) {
    const float* x = (const float*)d_in[0];
    const float* h = (const float*)d_in[1];
    const float* c = (const float*)d_in[2];
    const float* W = (const float*)d_in[3];
    const float* V = (const float*)d_in[4];
    const float* b = (const float*)d_in[5];
    float* out = (float*)d_out;

    cudaFuncSetAttribute(lstm_gemm, cudaFuncAttributeMaxDynamicSharedMemorySize, SMEM_TOTAL);

    prep_transpose<<<dim3(NDIM / 32, KDIM / 32), dim3(32, 8)>>>(W, V);
    prep_A<<<(int)(((size_t)BATCH * KDIM / 4) / 256), 256>>>(x, h);
    lstm_gemm<<<dim3(BATCH / MT, HIDDEN / 32), THREADS, SMEM_TOTAL>>>(c, b, out);
}